// round 1
// baseline (speedup 1.0000x reference)
#include <cuda_runtime.h>

#define UD 10000
#define ID 12000
#define KD 64
#define SPLIT 8
#define UT 157      // ceil(10000/64)
#define IT 188      // ceil(12000/64)
#define ISPAN 1500  // 12000/8
#define USPAN 1250  // 10000/8

// Scratch (static device globals — allocation-free rule)
__device__ float g_left_p[SPLIT][UD * KD];   // partials of norm_adj @ item_sv
__device__ float g_right_p[SPLIT][KD * ID];  // partials of user_sv^T @ adj
__device__ float g_left[UD * KD];            // reduced + scaled by 1/lambda
__device__ float g_right[KD * ID];           // reduced

typedef unsigned long long ull;

__device__ __forceinline__ ull pk2(float lo, float hi) {
    ull r; asm("mov.b64 %0,{%1,%2};" : "=l"(r) : "f"(lo), "f"(hi)); return r;
}
__device__ __forceinline__ void fma2(ull &d, ull a, ull b) {
    asm("fma.rn.f32x2 %0,%1,%2,%0;" : "+l"(d) : "l"(a), "l"(b));
}
__device__ __forceinline__ float2 up2(ull v) {
    float2 f; asm("mov.b64 {%0,%1},%2;" : "=f"(f.x), "=f"(f.y) : "l"(v)); return f;
}

// ---------------- K1: left_p[by] = norm_adj[:, iRange] @ item_sv[iRange, :] ----------------
// Block: 64 u-rows x 64 k (all), reduction chunk 32 i. 128 threads, micro 8u x 4k.
__global__ __launch_bounds__(128) void k1_kernel(const float* __restrict__ norm_adj,
                                                 const float* __restrict__ item_sv) {
    __shared__ float na_s[32][64];   // [ii][u]  (transposed)
    __shared__ float isv_s[32][64];  // [ii][k]
    const int t = threadIdx.x;
    const int u0 = blockIdx.x * 64;
    const int iBeg = blockIdx.y * ISPAN;
    const int iEnd = iBeg + ISPAN;
    const int u_base = (t & 7) * 8;
    const int k_base = (t >> 3) * 4;

    ull acc[4][4];  // [u-pair][k-offset]
#pragma unroll
    for (int a = 0; a < 4; a++)
#pragma unroll
        for (int b = 0; b < 4; b++) acc[a][b] = 0ull;

    for (int ic = iBeg; ic < iEnd; ic += 32) {
        // norm_adj tile [64u x 32i] -> na_s[ii][u]
#pragma unroll
        for (int q = 0; q < 4; q++) {
            int idx = t + q * 128;          // 0..511
            int u_lo = idx & 15;
            int c4 = (idx >> 4) & 7;
            int u_hi = idx >> 7;            // 0..3
            int ul = u_hi * 16 + u_lo;
            int gu = u0 + ul;
            int gi = ic + c4 * 4;
            float4 v = make_float4(0.f, 0.f, 0.f, 0.f);
            if (gu < UD && gi < iEnd)
                v = *(const float4*)&norm_adj[gu * ID + gi];
            na_s[c4 * 4 + 0][ul] = v.x;
            na_s[c4 * 4 + 1][ul] = v.y;
            na_s[c4 * 4 + 2][ul] = v.z;
            na_s[c4 * 4 + 3][ul] = v.w;
        }
        // item_sv tile [32i x 64k] -> isv_s (direct)
#pragma unroll
        for (int q = 0; q < 4; q++) {
            int idx = t + q * 128;
            int row = idx >> 4;             // 0..31
            int c4 = idx & 15;
            int gi = ic + row;
            float4 v = make_float4(0.f, 0.f, 0.f, 0.f);
            if (gi < iEnd)
                v = *(const float4*)&item_sv[gi * KD + c4 * 4];
            *(float4*)&isv_s[row][c4 * 4] = v;
        }
        __syncthreads();
#pragma unroll 8
        for (int ii = 0; ii < 32; ii++) {
            ulonglong2 A0 = *(const ulonglong2*)&na_s[ii][u_base];
            ulonglong2 A1 = *(const ulonglong2*)&na_s[ii][u_base + 4];
            float4 b4 = *(const float4*)&isv_s[ii][k_base];
            ull pa[4] = {A0.x, A0.y, A1.x, A1.y};
            ull pb[4] = {pk2(b4.x, b4.x), pk2(b4.y, b4.y), pk2(b4.z, b4.z), pk2(b4.w, b4.w)};
#pragma unroll
            for (int r = 0; r < 4; r++)
#pragma unroll
                for (int j = 0; j < 4; j++) fma2(acc[r][j], pa[r], pb[j]);
        }
        __syncthreads();
    }

    float* dst = g_left_p[blockIdx.y];
#pragma unroll
    for (int r = 0; r < 4; r++) {
        float2 f0 = up2(acc[r][0]), f1 = up2(acc[r][1]), f2 = up2(acc[r][2]), f3 = up2(acc[r][3]);
        int gu = u0 + u_base + 2 * r;
        if (gu < UD)     *(float4*)&dst[gu * KD + k_base]       = make_float4(f0.x, f1.x, f2.x, f3.x);
        if (gu + 1 < UD) *(float4*)&dst[(gu + 1) * KD + k_base] = make_float4(f0.y, f1.y, f2.y, f3.y);
    }
}

// ---------------- K2: right_p[by] = user_sv[uRange,:]^T @ adj[uRange, :] ----------------
// Block: 64 k (all) x 64 i, reduction chunk 32 u. 128 threads, micro 4k x 8i.
__global__ __launch_bounds__(128) void k2_kernel(const float* __restrict__ user_sv,
                                                 const float* __restrict__ adj) {
    __shared__ float usv_s[32][64];  // [uu][k]
    __shared__ float adj_s[32][64];  // [uu][i]
    const int t = threadIdx.x;
    const int i0 = blockIdx.x * 64;
    const int uBeg = blockIdx.y * USPAN;
    const int uEnd = uBeg + USPAN;
    const int i_base = (t & 7) * 8;
    const int k_base = (t >> 3) * 4;

    ull acc[4][4];  // [k-offset][i-pair]
#pragma unroll
    for (int a = 0; a < 4; a++)
#pragma unroll
        for (int b = 0; b < 4; b++) acc[a][b] = 0ull;

    for (int uc = uBeg; uc < uEnd; uc += 32) {
#pragma unroll
        for (int q = 0; q < 4; q++) {
            int idx = t + q * 128;
            int row = idx >> 4;
            int c4 = idx & 15;
            int gu = uc + row;
            float4 v = make_float4(0.f, 0.f, 0.f, 0.f);
            if (gu < uEnd)
                v = *(const float4*)&user_sv[gu * KD + c4 * 4];
            *(float4*)&usv_s[row][c4 * 4] = v;
        }
#pragma unroll
        for (int q = 0; q < 4; q++) {
            int idx = t + q * 128;
            int row = idx >> 4;
            int c4 = idx & 15;
            int gu = uc + row;
            int gi = i0 + c4 * 4;
            float4 v = make_float4(0.f, 0.f, 0.f, 0.f);
            if (gu < uEnd && gi < ID)
                v = *(const float4*)&adj[gu * ID + gi];
            *(float4*)&adj_s[row][c4 * 4] = v;
        }
        __syncthreads();
#pragma unroll 8
        for (int uu = 0; uu < 32; uu++) {
            float4 a4 = *(const float4*)&usv_s[uu][k_base];
            ulonglong2 B0 = *(const ulonglong2*)&adj_s[uu][i_base];
            ulonglong2 B1 = *(const ulonglong2*)&adj_s[uu][i_base + 4];
            ull pb[4] = {B0.x, B0.y, B1.x, B1.y};
            ull pa[4] = {pk2(a4.x, a4.x), pk2(a4.y, a4.y), pk2(a4.z, a4.z), pk2(a4.w, a4.w)};
#pragma unroll
            for (int r = 0; r < 4; r++)
#pragma unroll
                for (int j = 0; j < 4; j++) fma2(acc[r][j], pa[r], pb[j]);
        }
        __syncthreads();
    }

    float* dst = g_right_p[blockIdx.y];
    const int gi = i0 + i_base;
    if (gi < ID) {
#pragma unroll
        for (int kr = 0; kr < 4; kr++) {
            int k = k_base + kr;
            float2 f0 = up2(acc[kr][0]), f1 = up2(acc[kr][1]), f2 = up2(acc[kr][2]), f3 = up2(acc[kr][3]);
            *(float4*)&dst[k * ID + gi]     = make_float4(f0.x, f0.y, f1.x, f1.y);
            *(float4*)&dst[k * ID + gi + 4] = make_float4(f2.x, f2.y, f3.x, f3.y);
        }
    }
}

// ---------------- Reductions ----------------
__global__ void reduce_left_kernel(const float* __restrict__ lambda_mat) {
    int idx = blockIdx.x * blockDim.x + threadIdx.x;
    if (idx >= UD * KD) return;
    float s = 0.f;
#pragma unroll
    for (int p = 0; p < SPLIT; p++) s += g_left_p[p][idx];
    g_left[idx] = s / lambda_mat[idx & (KD - 1)];
}

__global__ void reduce_right_kernel() {
    int idx = blockIdx.x * blockDim.x + threadIdx.x;
    if (idx >= KD * ID) return;
    float s = 0.f;
#pragma unroll
    for (int p = 0; p < SPLIT; p++) s += g_right_p[p][idx];
    g_right[idx] = s;
}

// ---------------- K3: out = g_left @ g_right  (K=64 single pass) ----------------
// Block: 64u x 64i, 128 threads, micro 8u x 4i.
__global__ __launch_bounds__(128) void k3_kernel(float* __restrict__ out) {
    __shared__ float ls[64][64];  // [k][u] (transposed)
    __shared__ float rs[64][64];  // [k][i]
    const int t = threadIdx.x;
    const int u0 = blockIdx.x * 64;
    const int i0 = blockIdx.y * 64;
    const int u_base = (t & 7) * 8;
    const int i_base = (t >> 3) * 4;

    // g_left tile [64u x 64k] -> ls[k][u]
#pragma unroll
    for (int q = 0; q < 8; q++) {
        int idx = t + q * 128;            // 0..1023
        int u_lo = idx & 15;
        int c4 = (idx >> 4) & 15;
        int u_hi = idx >> 8;              // 0..3
        int ul = u_hi * 16 + u_lo;
        int gu = u0 + ul;
        float4 v = make_float4(0.f, 0.f, 0.f, 0.f);
        if (gu < UD) v = *(const float4*)&g_left[gu * KD + c4 * 4];
        ls[c4 * 4 + 0][ul] = v.x;
        ls[c4 * 4 + 1][ul] = v.y;
        ls[c4 * 4 + 2][ul] = v.z;
        ls[c4 * 4 + 3][ul] = v.w;
    }
    // g_right tile [64k x 64i] -> rs (direct)
#pragma unroll
    for (int q = 0; q < 8; q++) {
        int idx = t + q * 128;
        int row = idx >> 4;               // k
        int c4 = idx & 15;
        int gi = i0 + c4 * 4;
        float4 v = make_float4(0.f, 0.f, 0.f, 0.f);
        if (gi < ID) v = *(const float4*)&g_right[row * ID + gi];
        *(float4*)&rs[row][c4 * 4] = v;
    }
    __syncthreads();

    ull acc[4][4];  // [u-pair][i-offset]
#pragma unroll
    for (int a = 0; a < 4; a++)
#pragma unroll
        for (int b = 0; b < 4; b++) acc[a][b] = 0ull;

#pragma unroll 8
    for (int k = 0; k < 64; k++) {
        ulonglong2 A0 = *(const ulonglong2*)&ls[k][u_base];
        ulonglong2 A1 = *(const ulonglong2*)&ls[k][u_base + 4];
        float4 b4 = *(const float4*)&rs[k][i_base];
        ull pa[4] = {A0.x, A0.y, A1.x, A1.y};
        ull pb[4] = {pk2(b4.x, b4.x), pk2(b4.y, b4.y), pk2(b4.z, b4.z), pk2(b4.w, b4.w)};
#pragma unroll
        for (int r = 0; r < 4; r++)
#pragma unroll
            for (int j = 0; j < 4; j++) fma2(acc[r][j], pa[r], pb[j]);
    }

    const int gi = i0 + i_base;
    if (gi < ID) {
#pragma unroll
        for (int r = 0; r < 4; r++) {
            float2 f0 = up2(acc[r][0]), f1 = up2(acc[r][1]), f2 = up2(acc[r][2]), f3 = up2(acc[r][3]);
            int gu = u0 + u_base + 2 * r;
            if (gu < UD)
                *(float4*)&out[(size_t)gu * ID + gi] = make_float4(f0.x, f1.x, f2.x, f3.x);
            if (gu + 1 < UD)
                *(float4*)&out[(size_t)(gu + 1) * ID + gi] = make_float4(f0.y, f1.y, f2.y, f3.y);
        }
    }
}

extern "C" void kernel_launch(void* const* d_in, const int* in_sizes, int n_in,
                              void* d_out, int out_size) {
    const float* lambda_mat = (const float*)d_in[0];
    const float* user_sv    = (const float*)d_in[1];
    const float* item_sv    = (const float*)d_in[2];
    const float* adj_mat    = (const float*)d_in[3];
    const float* norm_adj   = (const float*)d_in[4];
    float* out = (float*)d_out;

    k1_kernel<<<dim3(UT, SPLIT), 128>>>(norm_adj, item_sv);
    k2_kernel<<<dim3(IT, SPLIT), 128>>>(user_sv, adj_mat);
    reduce_left_kernel<<<(UD * KD + 255) / 256, 256>>>(lambda_mat);
    reduce_right_kernel<<<(KD * ID + 255) / 256, 256>>>();
    k3_kernel<<<dim3(UT, IT), 128>>>(out);
}

// round 2
// speedup vs baseline: 1.0018x; 1.0018x over previous
#include <cuda_runtime.h>

#define UD 10000
#define ID 12000
#define KD 64
#define SPLIT 8
#define UT 157      // ceil(10000/64)
#define IT 188      // ceil(12000/64)
#define ISPAN 1500  // 12000/8
#define USPAN 1250  // 10000/8

// Scratch (static device globals — allocation-free rule)
__device__ float g_left_p[SPLIT][UD * KD];   // partials of norm_adj @ item_sv
__device__ float g_right_p[SPLIT][KD * ID];  // partials of user_sv^T @ adj
__device__ float g_left[UD * KD];            // reduced + scaled by 1/lambda
__device__ float g_right[KD * ID];           // reduced

typedef unsigned long long ull;

__device__ __forceinline__ ull pk2(float lo, float hi) {
    ull r; asm("mov.b64 %0,{%1,%2};" : "=l"(r) : "f"(lo), "f"(hi)); return r;
}
__device__ __forceinline__ void fma2(ull &d, ull a, ull b) {
    asm("fma.rn.f32x2 %0,%1,%2,%0;" : "+l"(d) : "l"(a), "l"(b));
}
__device__ __forceinline__ float2 up2(ull v) {
    float2 f; asm("mov.b64 {%0,%1},%2;" : "=f"(f.x), "=f"(f.y) : "l"(v)); return f;
}

// ---------------- K1: left_p[by] = norm_adj[:, iRange] @ item_sv[iRange, :] ----------------
// Block: 64 u-rows x 64 k (all), reduction chunk 32 i. 128 threads, micro 8u x 4k.
__global__ __launch_bounds__(128) void k1_kernel(const float* __restrict__ norm_adj,
                                                 const float* __restrict__ item_sv) {
    __shared__ float na_s[32][64];   // [ii][u]  (transposed)
    __shared__ float isv_s[32][64];  // [ii][k]
    const int t = threadIdx.x;
    const int u0 = blockIdx.x * 64;
    const int iBeg = blockIdx.y * ISPAN;
    const int iEnd = iBeg + ISPAN;
    const int u_base = (t & 7) * 8;
    const int k_base = (t >> 3) * 4;

    ull acc[4][4];  // [u-pair][k-offset]
#pragma unroll
    for (int a = 0; a < 4; a++)
#pragma unroll
        for (int b = 0; b < 4; b++) acc[a][b] = 0ull;

    for (int ic = iBeg; ic < iEnd; ic += 32) {
        // norm_adj tile [64u x 32i] -> na_s[ii][u]
#pragma unroll
        for (int q = 0; q < 4; q++) {
            int idx = t + q * 128;          // 0..511
            int u_lo = idx & 15;
            int c4 = (idx >> 4) & 7;
            int u_hi = idx >> 7;            // 0..3
            int ul = u_hi * 16 + u_lo;
            int gu = u0 + ul;
            int gi = ic + c4 * 4;
            float4 v = make_float4(0.f, 0.f, 0.f, 0.f);
            if (gu < UD && gi < iEnd)
                v = *(const float4*)&norm_adj[gu * ID + gi];
            na_s[c4 * 4 + 0][ul] = v.x;
            na_s[c4 * 4 + 1][ul] = v.y;
            na_s[c4 * 4 + 2][ul] = v.z;
            na_s[c4 * 4 + 3][ul] = v.w;
        }
        // item_sv tile [32i x 64k] -> isv_s (direct)
#pragma unroll
        for (int q = 0; q < 4; q++) {
            int idx = t + q * 128;
            int row = idx >> 4;             // 0..31
            int c4 = idx & 15;
            int gi = ic + row;
            float4 v = make_float4(0.f, 0.f, 0.f, 0.f);
            if (gi < iEnd)
                v = *(const float4*)&item_sv[gi * KD + c4 * 4];
            *(float4*)&isv_s[row][c4 * 4] = v;
        }
        __syncthreads();
#pragma unroll 8
        for (int ii = 0; ii < 32; ii++) {
            ulonglong2 A0 = *(const ulonglong2*)&na_s[ii][u_base];
            ulonglong2 A1 = *(const ulonglong2*)&na_s[ii][u_base + 4];
            float4 b4 = *(const float4*)&isv_s[ii][k_base];
            ull pa[4] = {A0.x, A0.y, A1.x, A1.y};
            ull pb[4] = {pk2(b4.x, b4.x), pk2(b4.y, b4.y), pk2(b4.z, b4.z), pk2(b4.w, b4.w)};
#pragma unroll
            for (int r = 0; r < 4; r++)
#pragma unroll
                for (int j = 0; j < 4; j++) fma2(acc[r][j], pa[r], pb[j]);
        }
        __syncthreads();
    }

    float* dst = g_left_p[blockIdx.y];
#pragma unroll
    for (int r = 0; r < 4; r++) {
        float2 f0 = up2(acc[r][0]), f1 = up2(acc[r][1]), f2 = up2(acc[r][2]), f3 = up2(acc[r][3]);
        int gu = u0 + u_base + 2 * r;
        if (gu < UD)     *(float4*)&dst[gu * KD + k_base]       = make_float4(f0.x, f1.x, f2.x, f3.x);
        if (gu + 1 < UD) *(float4*)&dst[(gu + 1) * KD + k_base] = make_float4(f0.y, f1.y, f2.y, f3.y);
    }
}

// ---------------- K2: right_p[by] = user_sv[uRange,:]^T @ adj[uRange, :] ----------------
// Block: 64 k (all) x 64 i, reduction chunk 32 u. 128 threads, micro 4k x 8i.
__global__ __launch_bounds__(128) void k2_kernel(const float* __restrict__ user_sv,
                                                 const float* __restrict__ adj) {
    __shared__ float usv_s[32][64];  // [uu][k]
    __shared__ float adj_s[32][64];  // [uu][i]
    const int t = threadIdx.x;
    const int i0 = blockIdx.x * 64;
    const int uBeg = blockIdx.y * USPAN;
    const int uEnd = uBeg + USPAN;
    const int i_base = (t & 7) * 8;
    const int k_base = (t >> 3) * 4;

    ull acc[4][4];  // [k-offset][i-pair]
#pragma unroll
    for (int a = 0; a < 4; a++)
#pragma unroll
        for (int b = 0; b < 4; b++) acc[a][b] = 0ull;

    for (int uc = uBeg; uc < uEnd; uc += 32) {
#pragma unroll
        for (int q = 0; q < 4; q++) {
            int idx = t + q * 128;
            int row = idx >> 4;
            int c4 = idx & 15;
            int gu = uc + row;
            float4 v = make_float4(0.f, 0.f, 0.f, 0.f);
            if (gu < uEnd)
                v = *(const float4*)&user_sv[gu * KD + c4 * 4];
            *(float4*)&usv_s[row][c4 * 4] = v;
        }
#pragma unroll
        for (int q = 0; q < 4; q++) {
            int idx = t + q * 128;
            int row = idx >> 4;
            int c4 = idx & 15;
            int gu = uc + row;
            int gi = i0 + c4 * 4;
            float4 v = make_float4(0.f, 0.f, 0.f, 0.f);
            if (gu < uEnd && gi < ID)
                v = *(const float4*)&adj[gu * ID + gi];
            *(float4*)&adj_s[row][c4 * 4] = v;
        }
        __syncthreads();
#pragma unroll 8
        for (int uu = 0; uu < 32; uu++) {
            float4 a4 = *(const float4*)&usv_s[uu][k_base];
            ulonglong2 B0 = *(const ulonglong2*)&adj_s[uu][i_base];
            ulonglong2 B1 = *(const ulonglong2*)&adj_s[uu][i_base + 4];
            ull pb[4] = {B0.x, B0.y, B1.x, B1.y};
            ull pa[4] = {pk2(a4.x, a4.x), pk2(a4.y, a4.y), pk2(a4.z, a4.z), pk2(a4.w, a4.w)};
#pragma unroll
            for (int r = 0; r < 4; r++)
#pragma unroll
                for (int j = 0; j < 4; j++) fma2(acc[r][j], pa[r], pb[j]);
        }
        __syncthreads();
    }

    float* dst = g_right_p[blockIdx.y];
    const int gi = i0 + i_base;
    if (gi < ID) {
#pragma unroll
        for (int kr = 0; kr < 4; kr++) {
            int k = k_base + kr;
            float2 f0 = up2(acc[kr][0]), f1 = up2(acc[kr][1]), f2 = up2(acc[kr][2]), f3 = up2(acc[kr][3]);
            *(float4*)&dst[k * ID + gi]     = make_float4(f0.x, f0.y, f1.x, f1.y);
            *(float4*)&dst[k * ID + gi + 4] = make_float4(f2.x, f2.y, f3.x, f3.y);
        }
    }
}

// ---------------- Reductions ----------------
__global__ void reduce_left_kernel(const float* __restrict__ lambda_mat) {
    int idx = blockIdx.x * blockDim.x + threadIdx.x;
    if (idx >= UD * KD) return;
    float s = 0.f;
#pragma unroll
    for (int p = 0; p < SPLIT; p++) s += g_left_p[p][idx];
    g_left[idx] = s / lambda_mat[idx & (KD - 1)];
}

__global__ void reduce_right_kernel() {
    int idx = blockIdx.x * blockDim.x + threadIdx.x;
    if (idx >= KD * ID) return;
    float s = 0.f;
#pragma unroll
    for (int p = 0; p < SPLIT; p++) s += g_right_p[p][idx];
    g_right[idx] = s;
}

// ---------------- K3: out = g_left @ g_right  (K=64 single pass) ----------------
// Block: 64u x 64i, 128 threads, micro 8u x 4i.
__global__ __launch_bounds__(128) void k3_kernel(float* __restrict__ out) {
    __shared__ float ls[64][64];  // [k][u] (transposed)
    __shared__ float rs[64][64];  // [k][i]
    const int t = threadIdx.x;
    const int u0 = blockIdx.x * 64;
    const int i0 = blockIdx.y * 64;
    const int u_base = (t & 7) * 8;
    const int i_base = (t >> 3) * 4;

    // g_left tile [64u x 64k] -> ls[k][u]
#pragma unroll
    for (int q = 0; q < 8; q++) {
        int idx = t + q * 128;            // 0..1023
        int u_lo = idx & 15;
        int c4 = (idx >> 4) & 15;
        int u_hi = idx >> 8;              // 0..3
        int ul = u_hi * 16 + u_lo;
        int gu = u0 + ul;
        float4 v = make_float4(0.f, 0.f, 0.f, 0.f);
        if (gu < UD) v = *(const float4*)&g_left[gu * KD + c4 * 4];
        ls[c4 * 4 + 0][ul] = v.x;
        ls[c4 * 4 + 1][ul] = v.y;
        ls[c4 * 4 + 2][ul] = v.z;
        ls[c4 * 4 + 3][ul] = v.w;
    }
    // g_right tile [64k x 64i] -> rs (direct)
#pragma unroll
    for (int q = 0; q < 8; q++) {
        int idx = t + q * 128;
        int row = idx >> 4;               // k
        int c4 = idx & 15;
        int gi = i0 + c4 * 4;
        float4 v = make_float4(0.f, 0.f, 0.f, 0.f);
        if (gi < ID) v = *(const float4*)&g_right[row * ID + gi];
        *(float4*)&rs[row][c4 * 4] = v;
    }
    __syncthreads();

    ull acc[4][4];  // [u-pair][i-offset]
#pragma unroll
    for (int a = 0; a < 4; a++)
#pragma unroll
        for (int b = 0; b < 4; b++) acc[a][b] = 0ull;

#pragma unroll 8
    for (int k = 0; k < 64; k++) {
        ulonglong2 A0 = *(const ulonglong2*)&ls[k][u_base];
        ulonglong2 A1 = *(const ulonglong2*)&ls[k][u_base + 4];
        float4 b4 = *(const float4*)&rs[k][i_base];
        ull pa[4] = {A0.x, A0.y, A1.x, A1.y};
        ull pb[4] = {pk2(b4.x, b4.x), pk2(b4.y, b4.y), pk2(b4.z, b4.z), pk2(b4.w, b4.w)};
#pragma unroll
        for (int r = 0; r < 4; r++)
#pragma unroll
            for (int j = 0; j < 4; j++) fma2(acc[r][j], pa[r], pb[j]);
    }

    const int gi = i0 + i_base;
    if (gi < ID) {
#pragma unroll
        for (int r = 0; r < 4; r++) {
            float2 f0 = up2(acc[r][0]), f1 = up2(acc[r][1]), f2 = up2(acc[r][2]), f3 = up2(acc[r][3]);
            int gu = u0 + u_base + 2 * r;
            if (gu < UD)
                *(float4*)&out[(size_t)gu * ID + gi] = make_float4(f0.x, f1.x, f2.x, f3.x);
            if (gu + 1 < UD)
                *(float4*)&out[(size_t)(gu + 1) * ID + gi] = make_float4(f0.y, f1.y, f2.y, f3.y);
        }
    }
}

extern "C" void kernel_launch(void* const* d_in, const int* in_sizes, int n_in,
                              void* d_out, int out_size) {
    const float* lambda_mat = (const float*)d_in[0];
    const float* user_sv    = (const float*)d_in[1];
    const float* item_sv    = (const float*)d_in[2];
    const float* adj_mat    = (const float*)d_in[3];
    const float* norm_adj   = (const float*)d_in[4];
    float* out = (float*)d_out;

    k1_kernel<<<dim3(UT, SPLIT), 128>>>(norm_adj, item_sv);
    k2_kernel<<<dim3(IT, SPLIT), 128>>>(user_sv, adj_mat);
    reduce_left_kernel<<<(UD * KD + 255) / 256, 256>>>(lambda_mat);
    reduce_right_kernel<<<(KD * ID + 255) / 256, 256>>>();
    k3_kernel<<<dim3(UT, IT), 128>>>(out);
}

// round 3
// speedup vs baseline: 1.0018x; 1.0000x over previous
#include <cuda_runtime.h>

#define UD 10000
#define ID 12000
#define KD 64
#define SPLIT 8
#define UT 157      // ceil(10000/64)
#define IT 188      // ceil(12000/64)
#define ISPAN 1500  // 12000/8
#define USPAN 1250  // 10000/8

// Scratch (static device globals — allocation-free rule)
__device__ float g_left_p[SPLIT][UD * KD];   // partials of norm_adj @ item_sv
__device__ float g_right_p[SPLIT][KD * ID];  // partials of user_sv^T @ adj
__device__ float g_left[UD * KD];            // reduced + scaled by 1/lambda
__device__ float g_right[KD * ID];           // reduced

typedef unsigned long long ull;

__device__ __forceinline__ ull pk2(float lo, float hi) {
    ull r; asm("mov.b64 %0,{%1,%2};" : "=l"(r) : "f"(lo), "f"(hi)); return r;
}
__device__ __forceinline__ void fma2(ull &d, ull a, ull b) {
    asm("fma.rn.f32x2 %0,%1,%2,%0;" : "+l"(d) : "l"(a), "l"(b));
}
__device__ __forceinline__ float2 up2(ull v) {
    float2 f; asm("mov.b64 {%0,%1},%2;" : "=f"(f.x), "=f"(f.y) : "l"(v)); return f;
}

// ---------------- K1: left_p[by] = norm_adj[:, iRange] @ item_sv[iRange, :] ----------------
// Block: 64 u-rows x 64 k (all), reduction chunk 32 i. 128 threads, micro 8u x 4k.
__global__ __launch_bounds__(128) void k1_kernel(const float* __restrict__ norm_adj,
                                                 const float* __restrict__ item_sv) {
    __shared__ float na_s[32][64];   // [ii][u]  (transposed)
    __shared__ float isv_s[32][64];  // [ii][k]
    const int t = threadIdx.x;
    const int u0 = blockIdx.x * 64;
    const int iBeg = blockIdx.y * ISPAN;
    const int iEnd = iBeg + ISPAN;
    const int u_base = (t & 7) * 8;
    const int k_base = (t >> 3) * 4;

    ull acc[4][4];  // [u-pair][k-offset]
#pragma unroll
    for (int a = 0; a < 4; a++)
#pragma unroll
        for (int b = 0; b < 4; b++) acc[a][b] = 0ull;

    for (int ic = iBeg; ic < iEnd; ic += 32) {
        // norm_adj tile [64u x 32i] -> na_s[ii][u]
#pragma unroll
        for (int q = 0; q < 4; q++) {
            int idx = t + q * 128;          // 0..511
            int u_lo = idx & 15;
            int c4 = (idx >> 4) & 7;
            int u_hi = idx >> 7;            // 0..3
            int ul = u_hi * 16 + u_lo;
            int gu = u0 + ul;
            int gi = ic + c4 * 4;
            float4 v = make_float4(0.f, 0.f, 0.f, 0.f);
            if (gu < UD && gi < iEnd)
                v = *(const float4*)&norm_adj[gu * ID + gi];
            na_s[c4 * 4 + 0][ul] = v.x;
            na_s[c4 * 4 + 1][ul] = v.y;
            na_s[c4 * 4 + 2][ul] = v.z;
            na_s[c4 * 4 + 3][ul] = v.w;
        }
        // item_sv tile [32i x 64k] -> isv_s (direct)
#pragma unroll
        for (int q = 0; q < 4; q++) {
            int idx = t + q * 128;
            int row = idx >> 4;             // 0..31
            int c4 = idx & 15;
            int gi = ic + row;
            float4 v = make_float4(0.f, 0.f, 0.f, 0.f);
            if (gi < iEnd)
                v = *(const float4*)&item_sv[gi * KD + c4 * 4];
            *(float4*)&isv_s[row][c4 * 4] = v;
        }
        __syncthreads();
#pragma unroll 8
        for (int ii = 0; ii < 32; ii++) {
            ulonglong2 A0 = *(const ulonglong2*)&na_s[ii][u_base];
            ulonglong2 A1 = *(const ulonglong2*)&na_s[ii][u_base + 4];
            float4 b4 = *(const float4*)&isv_s[ii][k_base];
            ull pa[4] = {A0.x, A0.y, A1.x, A1.y};
            ull pb[4] = {pk2(b4.x, b4.x), pk2(b4.y, b4.y), pk2(b4.z, b4.z), pk2(b4.w, b4.w)};
#pragma unroll
            for (int r = 0; r < 4; r++)
#pragma unroll
                for (int j = 0; j < 4; j++) fma2(acc[r][j], pa[r], pb[j]);
        }
        __syncthreads();
    }

    float* dst = g_left_p[blockIdx.y];
#pragma unroll
    for (int r = 0; r < 4; r++) {
        float2 f0 = up2(acc[r][0]), f1 = up2(acc[r][1]), f2 = up2(acc[r][2]), f3 = up2(acc[r][3]);
        int gu = u0 + u_base + 2 * r;
        if (gu < UD)     *(float4*)&dst[gu * KD + k_base]       = make_float4(f0.x, f1.x, f2.x, f3.x);
        if (gu + 1 < UD) *(float4*)&dst[(gu + 1) * KD + k_base] = make_float4(f0.y, f1.y, f2.y, f3.y);
    }
}

// ---------------- K2: right_p[by] = user_sv[uRange,:]^T @ adj[uRange, :] ----------------
// Block: 64 k (all) x 64 i, reduction chunk 32 u. 128 threads, micro 4k x 8i.
__global__ __launch_bounds__(128) void k2_kernel(const float* __restrict__ user_sv,
                                                 const float* __restrict__ adj) {
    __shared__ float usv_s[32][64];  // [uu][k]
    __shared__ float adj_s[32][64];  // [uu][i]
    const int t = threadIdx.x;
    const int i0 = blockIdx.x * 64;
    const int uBeg = blockIdx.y * USPAN;
    const int uEnd = uBeg + USPAN;
    const int i_base = (t & 7) * 8;
    const int k_base = (t >> 3) * 4;

    ull acc[4][4];  // [k-offset][i-pair]
#pragma unroll
    for (int a = 0; a < 4; a++)
#pragma unroll
        for (int b = 0; b < 4; b++) acc[a][b] = 0ull;

    for (int uc = uBeg; uc < uEnd; uc += 32) {
#pragma unroll
        for (int q = 0; q < 4; q++) {
            int idx = t + q * 128;
            int row = idx >> 4;
            int c4 = idx & 15;
            int gu = uc + row;
            float4 v = make_float4(0.f, 0.f, 0.f, 0.f);
            if (gu < uEnd)
                v = *(const float4*)&user_sv[gu * KD + c4 * 4];
            *(float4*)&usv_s[row][c4 * 4] = v;
        }
#pragma unroll
        for (int q = 0; q < 4; q++) {
            int idx = t + q * 128;
            int row = idx >> 4;
            int c4 = idx & 15;
            int gu = uc + row;
            int gi = i0 + c4 * 4;
            float4 v = make_float4(0.f, 0.f, 0.f, 0.f);
            if (gu < uEnd && gi < ID)
                v = *(const float4*)&adj[gu * ID + gi];
            *(float4*)&adj_s[row][c4 * 4] = v;
        }
        __syncthreads();
#pragma unroll 8
        for (int uu = 0; uu < 32; uu++) {
            float4 a4 = *(const float4*)&usv_s[uu][k_base];
            ulonglong2 B0 = *(const ulonglong2*)&adj_s[uu][i_base];
            ulonglong2 B1 = *(const ulonglong2*)&adj_s[uu][i_base + 4];
            ull pb[4] = {B0.x, B0.y, B1.x, B1.y};
            ull pa[4] = {pk2(a4.x, a4.x), pk2(a4.y, a4.y), pk2(a4.z, a4.z), pk2(a4.w, a4.w)};
#pragma unroll
            for (int r = 0; r < 4; r++)
#pragma unroll
                for (int j = 0; j < 4; j++) fma2(acc[r][j], pa[r], pb[j]);
        }
        __syncthreads();
    }

    float* dst = g_right_p[blockIdx.y];
    const int gi = i0 + i_base;
    if (gi < ID) {
#pragma unroll
        for (int kr = 0; kr < 4; kr++) {
            int k = k_base + kr;
            float2 f0 = up2(acc[kr][0]), f1 = up2(acc[kr][1]), f2 = up2(acc[kr][2]), f3 = up2(acc[kr][3]);
            *(float4*)&dst[k * ID + gi]     = make_float4(f0.x, f0.y, f1.x, f1.y);
            *(float4*)&dst[k * ID + gi + 4] = make_float4(f2.x, f2.y, f3.x, f3.y);
        }
    }
}

// ---------------- Reductions ----------------
__global__ void reduce_left_kernel(const float* __restrict__ lambda_mat) {
    int idx = blockIdx.x * blockDim.x + threadIdx.x;
    if (idx >= UD * KD) return;
    float s = 0.f;
#pragma unroll
    for (int p = 0; p < SPLIT; p++) s += g_left_p[p][idx];
    g_left[idx] = s / lambda_mat[idx & (KD - 1)];
}

__global__ void reduce_right_kernel() {
    int idx = blockIdx.x * blockDim.x + threadIdx.x;
    if (idx >= KD * ID) return;
    float s = 0.f;
#pragma unroll
    for (int p = 0; p < SPLIT; p++) s += g_right_p[p][idx];
    g_right[idx] = s;
}

// ---------------- K3: out = g_left @ g_right  (K=64 single pass) ----------------
// Block: 64u x 64i, 128 threads, micro 8u x 4i.
__global__ __launch_bounds__(128) void k3_kernel(float* __restrict__ out) {
    __shared__ float ls[64][64];  // [k][u] (transposed)
    __shared__ float rs[64][64];  // [k][i]
    const int t = threadIdx.x;
    const int u0 = blockIdx.x * 64;
    const int i0 = blockIdx.y * 64;
    const int u_base = (t & 7) * 8;
    const int i_base = (t >> 3) * 4;

    // g_left tile [64u x 64k] -> ls[k][u]
#pragma unroll
    for (int q = 0; q < 8; q++) {
        int idx = t + q * 128;            // 0..1023
        int u_lo = idx & 15;
        int c4 = (idx >> 4) & 15;
        int u_hi = idx >> 8;              // 0..3
        int ul = u_hi * 16 + u_lo;
        int gu = u0 + ul;
        float4 v = make_float4(0.f, 0.f, 0.f, 0.f);
        if (gu < UD) v = *(const float4*)&g_left[gu * KD + c4 * 4];
        ls[c4 * 4 + 0][ul] = v.x;
        ls[c4 * 4 + 1][ul] = v.y;
        ls[c4 * 4 + 2][ul] = v.z;
        ls[c4 * 4 + 3][ul] = v.w;
    }
    // g_right tile [64k x 64i] -> rs (direct)
#pragma unroll
    for (int q = 0; q < 8; q++) {
        int idx = t + q * 128;
        int row = idx >> 4;               // k
        int c4 = idx & 15;
        int gi = i0 + c4 * 4;
        float4 v = make_float4(0.f, 0.f, 0.f, 0.f);
        if (gi < ID) v = *(const float4*)&g_right[row * ID + gi];
        *(float4*)&rs[row][c4 * 4] = v;
    }
    __syncthreads();

    ull acc[4][4];  // [u-pair][i-offset]
#pragma unroll
    for (int a = 0; a < 4; a++)
#pragma unroll
        for (int b = 0; b < 4; b++) acc[a][b] = 0ull;

#pragma unroll 8
    for (int k = 0; k < 64; k++) {
        ulonglong2 A0 = *(const ulonglong2*)&ls[k][u_base];
        ulonglong2 A1 = *(const ulonglong2*)&ls[k][u_base + 4];
        float4 b4 = *(const float4*)&rs[k][i_base];
        ull pa[4] = {A0.x, A0.y, A1.x, A1.y};
        ull pb[4] = {pk2(b4.x, b4.x), pk2(b4.y, b4.y), pk2(b4.z, b4.z), pk2(b4.w, b4.w)};
#pragma unroll
        for (int r = 0; r < 4; r++)
#pragma unroll
            for (int j = 0; j < 4; j++) fma2(acc[r][j], pa[r], pb[j]);
    }

    const int gi = i0 + i_base;
    if (gi < ID) {
#pragma unroll
        for (int r = 0; r < 4; r++) {
            float2 f0 = up2(acc[r][0]), f1 = up2(acc[r][1]), f2 = up2(acc[r][2]), f3 = up2(acc[r][3]);
            int gu = u0 + u_base + 2 * r;
            if (gu < UD)
                *(float4*)&out[(size_t)gu * ID + gi] = make_float4(f0.x, f1.x, f2.x, f3.x);
            if (gu + 1 < UD)
                *(float4*)&out[(size_t)(gu + 1) * ID + gi] = make_float4(f0.y, f1.y, f2.y, f3.y);
        }
    }
}

extern "C" void kernel_launch(void* const* d_in, const int* in_sizes, int n_in,
                              void* d_out, int out_size) {
    const float* lambda_mat = (const float*)d_in[0];
    const float* user_sv    = (const float*)d_in[1];
    const float* item_sv    = (const float*)d_in[2];
    const float* adj_mat    = (const float*)d_in[3];
    const float* norm_adj   = (const float*)d_in[4];
    float* out = (float*)d_out;

    k1_kernel<<<dim3(UT, SPLIT), 128>>>(norm_adj, item_sv);
    k2_kernel<<<dim3(IT, SPLIT), 128>>>(user_sv, adj_mat);
    reduce_left_kernel<<<(UD * KD + 255) / 256, 256>>>(lambda_mat);
    reduce_right_kernel<<<(KD * ID + 255) / 256, 256>>>();
    k3_kernel<<<dim3(UT, IT), 128>>>(out);
}

// round 5
// speedup vs baseline: 3.5429x; 3.5365x over previous
#include <cuda_runtime.h>
#include <cuda_bf16.h>
#include <cstdint>

#define UD 10000
#define ID 12000
#define IPAD 12032   // 94*128
#define UPAD 10112   // 79*128

// ---------------- scratch ----------------
__device__ __align__(16) uint16_t g_iT_h[64 * IPAD], g_iT_l[64 * IPAD];  // item_sv^T bf16 hi/lo [k][i]
__device__ __align__(16) uint16_t g_uT_h[64 * UPAD], g_uT_l[64 * UPAD];  // user_sv^T bf16 hi/lo [k][u]
__device__ __align__(16) float    g_lp[3][(size_t)UD * 64];              // K1 partials [u][k]
__device__ __align__(16) float    g_rp[3][(size_t)ID * 64];              // K2 partials [i][k]
__device__ __align__(16) uint16_t g_l_h[UPAD * 64], g_l_l[UPAD * 64];    // left*invL bf16 [u][k]
__device__ __align__(16) uint16_t g_r_h[IPAD * 64], g_r_l[IPAD * 64];    // right^T bf16 [i][k]

// ---------------- helpers ----------------
__device__ __forceinline__ uint32_t smem_u32(const void* p) {
    uint32_t a;
    asm("{ .reg .u64 t; cvta.to.shared.u64 t, %1; cvt.u32.u64 %0, t; }" : "=r"(a) : "l"(p));
    return a;
}
// pack two floats -> bf16x2 hi + bf16x2 residual lo (x0 in low half)
__device__ __forceinline__ void split2(float x0, float x1, uint32_t& h, uint32_t& l) {
    asm("cvt.rn.bf16x2.f32 %0, %1, %2;" : "=r"(h) : "f"(x1), "f"(x0));
    float r0 = x0 - __uint_as_float(h << 16);
    float r1 = x1 - __uint_as_float(h & 0xffff0000u);
    asm("cvt.rn.bf16x2.f32 %0, %1, %2;" : "=r"(l) : "f"(r1), "f"(r0));
}
__device__ __forceinline__ void split1(float x, uint16_t& h, uint16_t& l) {
    uint32_t hh, ll;
    asm("cvt.rn.bf16x2.f32 %0, %1, %2;" : "=r"(hh) : "f"(0.f), "f"(x));
    float r = x - __uint_as_float(hh << 16);
    asm("cvt.rn.bf16x2.f32 %0, %1, %2;" : "=r"(ll) : "f"(0.f), "f"(r));
    h = (uint16_t)hh; l = (uint16_t)ll;
}
__device__ __forceinline__ void ldm4(uint32_t* r, uint32_t a) {
    asm volatile("ldmatrix.sync.aligned.m8n8.x4.shared.b16 {%0,%1,%2,%3},[%4];"
                 : "=r"(r[0]), "=r"(r[1]), "=r"(r[2]), "=r"(r[3]) : "r"(a));
}
__device__ __forceinline__ void ldm4t(uint32_t* r, uint32_t a) {
    asm volatile("ldmatrix.sync.aligned.m8n8.x4.trans.shared.b16 {%0,%1,%2,%3},[%4];"
                 : "=r"(r[0]), "=r"(r[1]), "=r"(r[2]), "=r"(r[3]) : "r"(a));
}
__device__ __forceinline__ void mma_bf16(float* d, const uint32_t* a, uint32_t b0, uint32_t b1) {
    asm volatile("mma.sync.aligned.m16n8k16.row.col.f32.bf16.bf16.f32 "
                 "{%0,%1,%2,%3},{%4,%5,%6,%7},{%8,%9},{%0,%1,%2,%3};"
                 : "+f"(d[0]), "+f"(d[1]), "+f"(d[2]), "+f"(d[3])
                 : "r"(a[0]), "r"(a[1]), "r"(a[2]), "r"(a[3]), "r"(b0), "r"(b1));
}

// ---------------- prep: tiled transpose + bf16 split ----------------
__global__ __launch_bounds__(256) void p_item(const float* __restrict__ isv) {
    __shared__ float st[64][65];
    const int t = threadIdx.x, i0 = blockIdx.x * 64;
#pragma unroll
    for (int q = 0; q < 16; q++) {
        int idx = t + q * 256;
        int il = idx >> 6, k = idx & 63, gi = i0 + il;
        st[il][k] = (gi < ID) ? isv[(size_t)gi * 64 + k] : 0.f;
    }
    __syncthreads();
#pragma unroll
    for (int q = 0; q < 16; q++) {
        int idx = t + q * 256;
        int k = idx >> 6, il = idx & 63;
        uint16_t h, l; split1(st[il][k], h, l);
        g_iT_h[(size_t)k * IPAD + i0 + il] = h;
        g_iT_l[(size_t)k * IPAD + i0 + il] = l;
    }
}
__global__ __launch_bounds__(256) void p_user(const float* __restrict__ usv) {
    __shared__ float st[64][65];
    const int t = threadIdx.x, u0 = blockIdx.x * 64;
#pragma unroll
    for (int q = 0; q < 16; q++) {
        int idx = t + q * 256;
        int ul = idx >> 6, k = idx & 63, gu = u0 + ul;
        st[ul][k] = (gu < UD) ? usv[(size_t)gu * 64 + k] : 0.f;
    }
    __syncthreads();
#pragma unroll
    for (int q = 0; q < 16; q++) {
        int idx = t + q * 256;
        int k = idx >> 6, ul = idx & 63;
        uint16_t h, l; split1(st[ul][k], h, l);
        g_uT_h[(size_t)k * UPAD + u0 + ul] = h;
        g_uT_l[(size_t)k * UPAD + u0 + ul] = l;
    }
}

// ---------------- K1: g_lp[s] = norm_adj @ item_sv  (M=128u, N=64k, Kchunk=32i) ----------------
// smem: Ah[128][40] @0, Al @10240, Bh[64][40] @20480, Bl @25600   (pitch 80B, conflict-free ldm)
__global__ __launch_bounds__(256, 2) void k1_mma(const float* __restrict__ A) {
    __shared__ char sm[30720];
    const int t = threadIdx.x, lane = t & 31, w = t >> 5;
    const uint32_t sb = smem_u32(sm);
    const int u0 = blockIdx.x * 128, ibase0 = blockIdx.y * 4000;
    const int m0 = (w >> 1) * 32, n0 = (w & 1) * 32;
    const uint32_t aoff = (uint32_t)(m0 + (lane & 15)) * 80 + ((lane >> 4) << 4);
    const uint32_t boff = (uint32_t)(n0 + (lane & 15)) * 80 + ((lane >> 4) << 4);
    const int brow = t >> 2, bc8 = (t & 3) << 3;

    float acc[2][4][4];
#pragma unroll
    for (int a = 0; a < 2; a++)
#pragma unroll
        for (int b = 0; b < 4; b++)
#pragma unroll
            for (int cc = 0; cc < 4; cc++) acc[a][b][cc] = 0.f;

    for (int c = 0; c < 125; c++) {
        const int ib = ibase0 + c * 32;
        float2 ar[8];
#pragma unroll
        for (int q = 0; q < 8; q++) {
            int pidx = t + q * 256;
            int ul = pidx >> 4, ic2 = (pidx & 15) << 1;
            int gu = u0 + ul;
            ar[q] = (gu < UD) ? *(const float2*)(A + (size_t)gu * ID + ib + ic2)
                              : make_float2(0.f, 0.f);
        }
        uint4 bh4 = *(const uint4*)(g_iT_h + (size_t)brow * IPAD + ib + bc8);
        uint4 bl4 = *(const uint4*)(g_iT_l + (size_t)brow * IPAD + ib + bc8);
        __syncthreads();
#pragma unroll
        for (int q = 0; q < 8; q++) {
            int pidx = t + q * 256;
            int ul = pidx >> 4, ic2 = (pidx & 15) << 1;
            uint32_t h, l; split2(ar[q].x, ar[q].y, h, l);
            *(uint32_t*)(sm + ul * 80 + ic2 * 2) = h;
            *(uint32_t*)(sm + 10240 + ul * 80 + ic2 * 2) = l;
        }
        *(uint4*)(sm + 20480 + brow * 80 + ((t & 3) << 4)) = bh4;
        *(uint4*)(sm + 25600 + brow * 80 + ((t & 3) << 4)) = bl4;
        __syncthreads();
#pragma unroll
        for (int ks = 0; ks < 2; ks++) {
            uint32_t bh[2][4], bl[2][4], ah[2][4], al[2][4];
#pragma unroll
            for (int p = 0; p < 2; p++) {
                ldm4(bh[p], sb + 20480 + boff + p * 1280 + ks * 32);
                ldm4(bl[p], sb + 25600 + boff + p * 1280 + ks * 32);
            }
#pragma unroll
            for (int mi = 0; mi < 2; mi++) {
                ldm4(ah[mi], sb + aoff + mi * 1280 + ks * 32);
                ldm4(al[mi], sb + 10240 + aoff + mi * 1280 + ks * 32);
            }
#pragma unroll
            for (int mi = 0; mi < 2; mi++)
#pragma unroll
                for (int nt = 0; nt < 4; nt++) {
                    int p = nt >> 1, j = nt & 1;
                    mma_bf16(acc[mi][nt], ah[mi], bh[p][j], bh[p][j + 2]);
                    mma_bf16(acc[mi][nt], ah[mi], bl[p][j], bl[p][j + 2]);
                    mma_bf16(acc[mi][nt], al[mi], bh[p][j], bh[p][j + 2]);
                }
        }
    }
    float* dst = g_lp[blockIdx.y];
    const int g = lane >> 2, tg = lane & 3;
#pragma unroll
    for (int mi = 0; mi < 2; mi++)
#pragma unroll
        for (int nt = 0; nt < 4; nt++) {
            int row = u0 + m0 + mi * 16 + g;
            int col = n0 + nt * 8 + tg * 2;
            if (row < UD)     *(float2*)(dst + (size_t)row * 64 + col)       = make_float2(acc[mi][nt][0], acc[mi][nt][1]);
            if (row + 8 < UD) *(float2*)(dst + (size_t)(row + 8) * 64 + col) = make_float2(acc[mi][nt][2], acc[mi][nt][3]);
        }
}

// ---------------- K2: g_rp[s][i][k] = adj^T @ user_sv  (M=128i, N=64k, Kchunk=32u) ----------------
// smem: Ah[32u][128+8 i] @0 (8704), Al @8704, Bh[64][40] @17408, Bl @22528
__global__ __launch_bounds__(256, 2) void k2_mma(const float* __restrict__ Adj) {
    __shared__ char sm[27648];
    const int t = threadIdx.x, lane = t & 31, w = t >> 5;
    const uint32_t sb = smem_u32(sm);
    const int i0 = blockIdx.x * 128, ubase0 = blockIdx.y * 3360;
    const int m0 = (w >> 1) * 32, n0 = (w & 1) * 32;
    const uint32_t aofft = (uint32_t)((lane & 7) + ((lane >> 4) << 3)) * 272
                         + (uint32_t)(m0 + (((lane >> 3) & 1) << 3)) * 2;
    const uint32_t boff = (uint32_t)(n0 + (lane & 15)) * 80 + ((lane >> 4) << 4);
    const int brow = t >> 2, bc8 = (t & 3) << 3;

    float acc[2][4][4];
#pragma unroll
    for (int a = 0; a < 2; a++)
#pragma unroll
        for (int b = 0; b < 4; b++)
#pragma unroll
            for (int cc = 0; cc < 4; cc++) acc[a][b][cc] = 0.f;

    for (int c = 0; c < 105; c++) {
        const int ub = ubase0 + c * 32;
        float2 ar[8];
#pragma unroll
        for (int q = 0; q < 8; q++) {
            int pidx = t + q * 256;
            int ul = pidx >> 6, i2 = (pidx & 63) << 1;
            int gu = ub + ul;
            ar[q] = (gu < UD) ? *(const float2*)(Adj + (size_t)gu * ID + i0 + i2)
                              : make_float2(0.f, 0.f);
        }
        uint4 bh4 = *(const uint4*)(g_uT_h + (size_t)brow * UPAD + ub + bc8);
        uint4 bl4 = *(const uint4*)(g_uT_l + (size_t)brow * UPAD + ub + bc8);
        __syncthreads();
#pragma unroll
        for (int q = 0; q < 8; q++) {
            int pidx = t + q * 256;
            int ul = pidx >> 6, i2 = (pidx & 63) << 1;
            uint32_t h, l; split2(ar[q].x, ar[q].y, h, l);
            *(uint32_t*)(sm + ul * 272 + i2 * 2) = h;
            *(uint32_t*)(sm + 8704 + ul * 272 + i2 * 2) = l;
        }
        *(uint4*)(sm + 17408 + brow * 80 + ((t & 3) << 4)) = bh4;
        *(uint4*)(sm + 22528 + brow * 80 + ((t & 3) << 4)) = bl4;
        __syncthreads();
#pragma unroll
        for (int ks = 0; ks < 2; ks++) {
            uint32_t bh[2][4], bl[2][4], ah[2][4], al[2][4];
#pragma unroll
            for (int p = 0; p < 2; p++) {
                ldm4(bh[p], sb + 17408 + boff + p * 1280 + ks * 32);
                ldm4(bl[p], sb + 22528 + boff + p * 1280 + ks * 32);
            }
#pragma unroll
            for (int mi = 0; mi < 2; mi++) {
                ldm4t(ah[mi], sb + aofft + mi * 32 + ks * 4352);
                ldm4t(al[mi], sb + 8704 + aofft + mi * 32 + ks * 4352);
            }
#pragma unroll
            for (int mi = 0; mi < 2; mi++)
#pragma unroll
                for (int nt = 0; nt < 4; nt++) {
                    int p = nt >> 1, j = nt & 1;
                    mma_bf16(acc[mi][nt], ah[mi], bh[p][j], bh[p][j + 2]);
                    mma_bf16(acc[mi][nt], ah[mi], bl[p][j], bl[p][j + 2]);
                    mma_bf16(acc[mi][nt], al[mi], bh[p][j], bh[p][j + 2]);
                }
        }
    }
    float* dst = g_rp[blockIdx.y];
    const int g = lane >> 2, tg = lane & 3;
#pragma unroll
    for (int mi = 0; mi < 2; mi++)
#pragma unroll
        for (int nt = 0; nt < 4; nt++) {
            int row = i0 + m0 + mi * 16 + g;
            int col = n0 + nt * 8 + tg * 2;
            if (row < ID)     *(float2*)(dst + (size_t)row * 64 + col)       = make_float2(acc[mi][nt][0], acc[mi][nt][1]);
            if (row + 8 < ID) *(float2*)(dst + (size_t)(row + 8) * 64 + col) = make_float2(acc[mi][nt][2], acc[mi][nt][3]);
        }
}

// ---------------- reductions + bf16 split ----------------
__global__ __launch_bounds__(256) void red_l(const float* __restrict__ lam) {
    int idx = blockIdx.x * 256 + threadIdx.x;
    if (idx >= UPAD * 64) return;
    int u = idx >> 6;
    float v = 0.f;
    if (u < UD) v = (g_lp[0][idx] + g_lp[1][idx] + g_lp[2][idx]) / lam[idx & 63];
    split1(v, g_l_h[idx], g_l_l[idx]);
}
__global__ __launch_bounds__(256) void red_r() {
    int idx = blockIdx.x * 256 + threadIdx.x;
    if (idx >= IPAD * 64) return;
    int i = idx >> 6;
    float v = 0.f;
    if (i < ID) v = g_rp[0][idx] + g_rp[1][idx] + g_rp[2][idx];
    split1(v, g_r_h[idx], g_r_l[idx]);
}

// ---------------- K3: out[u][i] = g_l @ g_r^T  (M=128u, N=128i, K=64 single pass) ----------------
// dyn smem: Ah[128][72] @0, Al @18432, Bh @36864, Bl @55296  (pitch 144B)
__global__ __launch_bounds__(256, 2) void k3_mma(float* __restrict__ out) {
    extern __shared__ __align__(16) char sm[];
    const int t = threadIdx.x, lane = t & 31, w = t >> 5;
    const uint32_t sb = smem_u32(sm);
    const int u0 = blockIdx.x * 128, i0 = blockIdx.y * 128;
    const int m0 = (w >> 2) * 64, n0 = (w & 3) * 32;
    const uint32_t abase = (uint32_t)(m0 + (lane & 15)) * 144 + ((lane >> 4) << 4);
    const uint32_t bbase = (uint32_t)(n0 + (lane & 15)) * 144 + ((lane >> 4) << 4);

#pragma unroll
    for (int q = 0; q < 4; q++) {
        int idx = t + q * 256;
        int row = idx >> 3, c8 = (idx & 7) << 3;
        *(uint4*)(sm + row * 144 + c8 * 2)         = *(const uint4*)(g_l_h + (size_t)(u0 + row) * 64 + c8);
        *(uint4*)(sm + 18432 + row * 144 + c8 * 2) = *(const uint4*)(g_l_l + (size_t)(u0 + row) * 64 + c8);
        *(uint4*)(sm + 36864 + row * 144 + c8 * 2) = *(const uint4*)(g_r_h + (size_t)(i0 + row) * 64 + c8);
        *(uint4*)(sm + 55296 + row * 144 + c8 * 2) = *(const uint4*)(g_r_l + (size_t)(i0 + row) * 64 + c8);
    }
    __syncthreads();

    float acc[4][4][4];
#pragma unroll
    for (int a = 0; a < 4; a++)
#pragma unroll
        for (int b = 0; b < 4; b++)
#pragma unroll
            for (int cc = 0; cc < 4; cc++) acc[a][b][cc] = 0.f;

#pragma unroll
    for (int ks = 0; ks < 4; ks++) {
        uint32_t bh[2][4], bl[2][4];
#pragma unroll
        for (int p = 0; p < 2; p++) {
            ldm4(bh[p], sb + 36864 + bbase + p * 2304 + ks * 32);
            ldm4(bl[p], sb + 55296 + bbase + p * 2304 + ks * 32);
        }
#pragma unroll
        for (int mi = 0; mi < 4; mi++) {
            uint32_t ah[4], al[4];
            ldm4(ah, sb + abase + mi * 2304 + ks * 32);
            ldm4(al, sb + 18432 + abase + mi * 2304 + ks * 32);
#pragma unroll
            for (int nt = 0; nt < 4; nt++) {
                int p = nt >> 1, j = nt & 1;
                mma_bf16(acc[mi][nt], ah, bh[p][j], bh[p][j + 2]);
                mma_bf16(acc[mi][nt], ah, bl[p][j], bl[p][j + 2]);
                mma_bf16(acc[mi][nt], al, bh[p][j], bh[p][j + 2]);
            }
        }
    }

    const int g = lane >> 2, tg = lane & 3;
#pragma unroll
    for (int mi = 0; mi < 4; mi++)
#pragma unroll
        for (int nt = 0; nt < 4; nt++) {
            int row = u0 + m0 + mi * 16 + g;
            int col = i0 + n0 + nt * 8 + tg * 2;
            if (col < ID) {
                if (row < UD)     *(float2*)(out + (size_t)row * ID + col)       = make_float2(acc[mi][nt][0], acc[mi][nt][1]);
                if (row + 8 < UD) *(float2*)(out + (size_t)(row + 8) * ID + col) = make_float2(acc[mi][nt][2], acc[mi][nt][3]);
            }
        }
}

// ---------------- launch ----------------
extern "C" void kernel_launch(void* const* d_in, const int* in_sizes, int n_in,
                              void* d_out, int out_size) {
    const float* lambda_mat = (const float*)d_in[0];
    const float* user_sv    = (const float*)d_in[1];
    const float* item_sv    = (const float*)d_in[2];
    const float* adj_mat    = (const float*)d_in[3];
    const float* norm_adj   = (const float*)d_in[4];
    float* out = (float*)d_out;

    cudaFuncSetAttribute(k3_mma, cudaFuncAttributeMaxDynamicSharedMemorySize, 73728);

    p_item<<<IPAD / 64, 256>>>(item_sv);
    p_user<<<UPAD / 64, 256>>>(user_sv);
    k1_mma<<<dim3(79, 3), 256>>>(norm_adj);
    k2_mma<<<dim3(94, 3), 256>>>(adj_mat);
    red_l<<<(UPAD * 64) / 256, 256>>>(lambda_mat);
    red_r<<<(IPAD * 64) / 256, 256>>>();
    k3_mma<<<dim3(79, 94), 256, 73728>>>(out);
}

// round 6
// speedup vs baseline: 3.7897x; 1.0697x over previous
#include <cuda_runtime.h>
#include <cuda_bf16.h>
#include <cstdint>

#define UD 10000
#define ID 12000
#define IPAD 12032   // 94*128
#define UPAD 10112   // 79*128

// ---------------- scratch ----------------
__device__ __align__(16) uint16_t g_iT_h[64 * IPAD], g_iT_l[64 * IPAD];  // item_sv^T bf16 hi/lo [k][i]
__device__ __align__(16) uint16_t g_uT_h[64 * UPAD], g_uT_l[64 * UPAD];  // user_sv^T bf16 hi/lo [k][u]
__device__ __align__(16) float    g_lp[3][(size_t)UD * 64];              // K1 partials [u][k]
__device__ __align__(16) float    g_rp[3][(size_t)ID * 64];              // K2 partials [i][k]
__device__ __align__(16) uint16_t g_l_h[UPAD * 64], g_l_l[UPAD * 64];    // left*invL bf16 [u][k]
__device__ __align__(16) uint16_t g_r_h[IPAD * 64], g_r_l[IPAD * 64];    // right^T bf16 [i][k]

// ---------------- helpers ----------------
__device__ __forceinline__ uint32_t smem_u32(const void* p) {
    uint32_t a;
    asm("{ .reg .u64 t; cvta.to.shared.u64 t, %1; cvt.u32.u64 %0, t; }" : "=r"(a) : "l"(p));
    return a;
}
__device__ __forceinline__ void split2(float x0, float x1, uint32_t& h, uint32_t& l) {
    asm("cvt.rn.bf16x2.f32 %0, %1, %2;" : "=r"(h) : "f"(x1), "f"(x0));
    float r0 = x0 - __uint_as_float(h << 16);
    float r1 = x1 - __uint_as_float(h & 0xffff0000u);
    asm("cvt.rn.bf16x2.f32 %0, %1, %2;" : "=r"(l) : "f"(r1), "f"(r0));
}
__device__ __forceinline__ void split1(float x, uint16_t& h, uint16_t& l) {
    uint32_t hh, ll;
    asm("cvt.rn.bf16x2.f32 %0, %1, %2;" : "=r"(hh) : "f"(0.f), "f"(x));
    float r = x - __uint_as_float(hh << 16);
    asm("cvt.rn.bf16x2.f32 %0, %1, %2;" : "=r"(ll) : "f"(0.f), "f"(r));
    h = (uint16_t)hh; l = (uint16_t)ll;
}
__device__ __forceinline__ void ldm4(uint32_t* r, uint32_t a) {
    asm volatile("ldmatrix.sync.aligned.m8n8.x4.shared.b16 {%0,%1,%2,%3},[%4];"
                 : "=r"(r[0]), "=r"(r[1]), "=r"(r[2]), "=r"(r[3]) : "r"(a));
}
__device__ __forceinline__ void ldm4t(uint32_t* r, uint32_t a) {
    asm volatile("ldmatrix.sync.aligned.m8n8.x4.trans.shared.b16 {%0,%1,%2,%3},[%4];"
                 : "=r"(r[0]), "=r"(r[1]), "=r"(r[2]), "=r"(r[3]) : "r"(a));
}
__device__ __forceinline__ void mma_bf16(float* d, const uint32_t* a, uint32_t b0, uint32_t b1) {
    asm volatile("mma.sync.aligned.m16n8k16.row.col.f32.bf16.bf16.f32 "
                 "{%0,%1,%2,%3},{%4,%5,%6,%7},{%8,%9},{%0,%1,%2,%3};"
                 : "+f"(d[0]), "+f"(d[1]), "+f"(d[2]), "+f"(d[3])
                 : "r"(a[0]), "r"(a[1]), "r"(a[2]), "r"(a[3]), "r"(b0), "r"(b1));
}

// ---------------- prep: tiled transpose + bf16 split ----------------
__global__ __launch_bounds__(256) void p_item(const float* __restrict__ isv) {
    __shared__ float st[64][65];
    const int t = threadIdx.x, i0 = blockIdx.x * 64;
#pragma unroll
    for (int q = 0; q < 16; q++) {
        int idx = t + q * 256;
        int il = idx >> 6, k = idx & 63, gi = i0 + il;
        st[il][k] = (gi < ID) ? isv[(size_t)gi * 64 + k] : 0.f;
    }
    __syncthreads();
#pragma unroll
    for (int q = 0; q < 16; q++) {
        int idx = t + q * 256;
        int k = idx >> 6, il = idx & 63;
        uint16_t h, l; split1(st[il][k], h, l);
        g_iT_h[(size_t)k * IPAD + i0 + il] = h;
        g_iT_l[(size_t)k * IPAD + i0 + il] = l;
    }
}
__global__ __launch_bounds__(256) void p_user(const float* __restrict__ usv) {
    __shared__ float st[64][65];
    const int t = threadIdx.x, u0 = blockIdx.x * 64;
#pragma unroll
    for (int q = 0; q < 16; q++) {
        int idx = t + q * 256;
        int ul = idx >> 6, k = idx & 63, gu = u0 + ul;
        st[ul][k] = (gu < UD) ? usv[(size_t)gu * 64 + k] : 0.f;
    }
    __syncthreads();
#pragma unroll
    for (int q = 0; q < 16; q++) {
        int idx = t + q * 256;
        int k = idx >> 6, ul = idx & 63;
        uint16_t h, l; split1(st[ul][k], h, l);
        g_uT_h[(size_t)k * UPAD + u0 + ul] = h;
        g_uT_l[(size_t)k * UPAD + u0 + ul] = l;
    }
}

// ---------------- K1: g_lp[s] = norm_adj @ item_sv  (M=128u, N=64k, Kchunk=32i, 2-buf pipelined) ---
// dyn smem 61440: Ah[b] @ b*10240, Al[b] @ 20480+b*10240, Bh[b] @ 40960+b*5120, Bl[b] @ 51200+b*5120
__global__ __launch_bounds__(256, 2) void k1_mma(const float* __restrict__ A) {
    extern __shared__ __align__(16) char sm[];
    const int t = threadIdx.x, lane = t & 31, w = t >> 5;
    const uint32_t sb = smem_u32(sm);
    const int u0 = blockIdx.x * 128, ibase0 = blockIdx.y * 4000;
    const int m0 = (w >> 1) * 32, n0 = (w & 1) * 32;
    const uint32_t aoff = (uint32_t)(m0 + (lane & 15)) * 80 + ((lane >> 4) << 4);
    const uint32_t boff = (uint32_t)(n0 + (lane & 15)) * 80 + ((lane >> 4) << 4);
    const int brow = t >> 2, bc8 = (t & 3) << 3;

    float acc[2][4][4];
#pragma unroll
    for (int a = 0; a < 2; a++)
#pragma unroll
        for (int b = 0; b < 4; b++)
#pragma unroll
            for (int cc = 0; cc < 4; cc++) acc[a][b][cc] = 0.f;

    float2 ar[8]; uint4 b4h, b4l;

    auto LDGf = [&](int c) {
        const int ib = ibase0 + c * 32;
#pragma unroll
        for (int q = 0; q < 8; q++) {
            int pidx = t + q * 256;
            int aul = pidx >> 4, ic2 = (pidx & 15) << 1;
            int gu = u0 + aul;
            ar[q] = (gu < UD) ? *(const float2*)(A + (size_t)gu * ID + ib + ic2)
                              : make_float2(0.f, 0.f);
        }
        b4h = *(const uint4*)(g_iT_h + (size_t)brow * IPAD + ib + bc8);
        b4l = *(const uint4*)(g_iT_l + (size_t)brow * IPAD + ib + bc8);
    };
    auto STSf = [&](int b) {
        char* ab = sm + b * 10240;
        char* al = sm + 20480 + b * 10240;
#pragma unroll
        for (int q = 0; q < 8; q++) {
            int pidx = t + q * 256;
            int aul = pidx >> 4, ic2 = (pidx & 15) << 1;
            uint32_t h, l; split2(ar[q].x, ar[q].y, h, l);
            *(uint32_t*)(ab + aul * 80 + ic2 * 2) = h;
            *(uint32_t*)(al + aul * 80 + ic2 * 2) = l;
        }
        *(uint4*)(sm + 40960 + b * 5120 + brow * 80 + ((t & 3) << 4)) = b4h;
        *(uint4*)(sm + 51200 + b * 5120 + brow * 80 + ((t & 3) << 4)) = b4l;
    };

    LDGf(0);
    STSf(0);
    __syncthreads();

    for (int c = 0; c < 125; c++) {
        const int b = c & 1;
        if (c + 1 < 125) LDGf(c + 1);
        const uint32_t bah = sb + b * 10240,        bal = sb + 20480 + b * 10240;
        const uint32_t bbh = sb + 40960 + b * 5120, bbl = sb + 51200 + b * 5120;
#pragma unroll
        for (int ks = 0; ks < 2; ks++) {
            uint32_t bh[2][4], bl[2][4], ah[2][4], al[2][4];
#pragma unroll
            for (int p = 0; p < 2; p++) {
                ldm4(bh[p], bbh + boff + p * 1280 + ks * 32);
                ldm4(bl[p], bbl + boff + p * 1280 + ks * 32);
            }
#pragma unroll
            for (int mi = 0; mi < 2; mi++) {
                ldm4(ah[mi], bah + aoff + mi * 1280 + ks * 32);
                ldm4(al[mi], bal + aoff + mi * 1280 + ks * 32);
            }
#pragma unroll
            for (int mi = 0; mi < 2; mi++)
#pragma unroll
                for (int nt = 0; nt < 4; nt++) {
                    int p = nt >> 1, j = nt & 1;
                    mma_bf16(acc[mi][nt], ah[mi], bh[p][j], bh[p][j + 2]);
                    mma_bf16(acc[mi][nt], ah[mi], bl[p][j], bl[p][j + 2]);
                    mma_bf16(acc[mi][nt], al[mi], bh[p][j], bh[p][j + 2]);
                }
        }
        if (c + 1 < 125) STSf(b ^ 1);
        __syncthreads();
    }

    float* dst = g_lp[blockIdx.y];
    const int g = lane >> 2, tg = lane & 3;
#pragma unroll
    for (int mi = 0; mi < 2; mi++)
#pragma unroll
        for (int nt = 0; nt < 4; nt++) {
            int row = u0 + m0 + mi * 16 + g;
            int col = n0 + nt * 8 + tg * 2;
            if (row < UD)     *(float2*)(dst + (size_t)row * 64 + col)       = make_float2(acc[mi][nt][0], acc[mi][nt][1]);
            if (row + 8 < UD) *(float2*)(dst + (size_t)(row + 8) * 64 + col) = make_float2(acc[mi][nt][2], acc[mi][nt][3]);
        }
}

// ---------------- K2: g_rp[s][i][k] = adj^T @ user_sv  (M=128i, N=64k, Kchunk=32u, 2-buf pipelined) -
// dyn smem 55296: Ah[b] @ b*8704, Al[b] @ 17408+b*8704, Bh[b] @ 34816+b*5120, Bl[b] @ 45056+b*5120
__global__ __launch_bounds__(256, 2) void k2_mma(const float* __restrict__ Adj) {
    extern __shared__ __align__(16) char sm[];
    const int t = threadIdx.x, lane = t & 31, w = t >> 5;
    const uint32_t sb = smem_u32(sm);
    const int i0 = blockIdx.x * 128, ubase0 = blockIdx.y * 3360;
    const int m0 = (w >> 1) * 32, n0 = (w & 1) * 32;
    const uint32_t aofft = (uint32_t)((lane & 7) + ((lane >> 4) << 3)) * 272
                         + (uint32_t)(m0 + (((lane >> 3) & 1) << 3)) * 2;
    const uint32_t boff = (uint32_t)(n0 + (lane & 15)) * 80 + ((lane >> 4) << 4);
    const int brow = t >> 2, bc8 = (t & 3) << 3;

    float acc[2][4][4];
#pragma unroll
    for (int a = 0; a < 2; a++)
#pragma unroll
        for (int b = 0; b < 4; b++)
#pragma unroll
            for (int cc = 0; cc < 4; cc++) acc[a][b][cc] = 0.f;

    float2 ar[8]; uint4 b4h, b4l;

    auto LDGf = [&](int c) {
        const int ub = ubase0 + c * 32;
#pragma unroll
        for (int q = 0; q < 8; q++) {
            int pidx = t + q * 256;
            int aul = pidx >> 6, i2 = (pidx & 63) << 1;
            int gu = ub + aul;
            ar[q] = (gu < UD) ? *(const float2*)(Adj + (size_t)gu * ID + i0 + i2)
                              : make_float2(0.f, 0.f);
        }
        b4h = *(const uint4*)(g_uT_h + (size_t)brow * UPAD + ub + bc8);
        b4l = *(const uint4*)(g_uT_l + (size_t)brow * UPAD + ub + bc8);
    };
    auto STSf = [&](int b) {
        char* ab = sm + b * 8704;
        char* al = sm + 17408 + b * 8704;
#pragma unroll
        for (int q = 0; q < 8; q++) {
            int pidx = t + q * 256;
            int aul = pidx >> 6, i2 = (pidx & 63) << 1;
            uint32_t h, l; split2(ar[q].x, ar[q].y, h, l);
            *(uint32_t*)(ab + aul * 272 + i2 * 2) = h;
            *(uint32_t*)(al + aul * 272 + i2 * 2) = l;
        }
        *(uint4*)(sm + 34816 + b * 5120 + brow * 80 + ((t & 3) << 4)) = b4h;
        *(uint4*)(sm + 45056 + b * 5120 + brow * 80 + ((t & 3) << 4)) = b4l;
    };

    LDGf(0);
    STSf(0);
    __syncthreads();

    for (int c = 0; c < 105; c++) {
        const int b = c & 1;
        if (c + 1 < 105) LDGf(c + 1);
        const uint32_t bah = sb + b * 8704,         bal = sb + 17408 + b * 8704;
        const uint32_t bbh = sb + 34816 + b * 5120, bbl = sb + 45056 + b * 5120;
#pragma unroll
        for (int ks = 0; ks < 2; ks++) {
            uint32_t bh[2][4], bl[2][4], ah[2][4], al[2][4];
#pragma unroll
            for (int p = 0; p < 2; p++) {
                ldm4(bh[p], bbh + boff + p * 1280 + ks * 32);
                ldm4(bl[p], bbl + boff + p * 1280 + ks * 32);
            }
#pragma unroll
            for (int mi = 0; mi < 2; mi++) {
                ldm4t(ah[mi], bah + aofft + mi * 32 + ks * 4352);
                ldm4t(al[mi], bal + aofft + mi * 32 + ks * 4352);
            }
#pragma unroll
            for (int mi = 0; mi < 2; mi++)
#pragma unroll
                for (int nt = 0; nt < 4; nt++) {
                    int p = nt >> 1, j = nt & 1;
                    mma_bf16(acc[mi][nt], ah[mi], bh[p][j], bh[p][j + 2]);
                    mma_bf16(acc[mi][nt], ah[mi], bl[p][j], bl[p][j + 2]);
                    mma_bf16(acc[mi][nt], al[mi], bh[p][j], bh[p][j + 2]);
                }
        }
        if (c + 1 < 105) STSf(b ^ 1);
        __syncthreads();
    }

    float* dst = g_rp[blockIdx.y];
    const int g = lane >> 2, tg = lane & 3;
#pragma unroll
    for (int mi = 0; mi < 2; mi++)
#pragma unroll
        for (int nt = 0; nt < 4; nt++) {
            int row = i0 + m0 + mi * 16 + g;
            int col = n0 + nt * 8 + tg * 2;
            if (row < ID)     *(float2*)(dst + (size_t)row * 64 + col)       = make_float2(acc[mi][nt][0], acc[mi][nt][1]);
            if (row + 8 < ID) *(float2*)(dst + (size_t)(row + 8) * 64 + col) = make_float2(acc[mi][nt][2], acc[mi][nt][3]);
        }
}

// ---------------- reductions + bf16 split ----------------
__global__ __launch_bounds__(256) void red_l(const float* __restrict__ lam) {
    int idx = blockIdx.x * 256 + threadIdx.x;
    if (idx >= UPAD * 64) return;
    int u = idx >> 6;
    float v = 0.f;
    if (u < UD) v = (g_lp[0][idx] + g_lp[1][idx] + g_lp[2][idx]) / lam[idx & 63];
    split1(v, g_l_h[idx], g_l_l[idx]);
}
__global__ __launch_bounds__(256) void red_r() {
    int idx = blockIdx.x * 256 + threadIdx.x;
    if (idx >= IPAD * 64) return;
    int i = idx >> 6;
    float v = 0.f;
    if (i < ID) v = g_rp[0][idx] + g_rp[1][idx] + g_rp[2][idx];
    split1(v, g_r_h[idx], g_r_l[idx]);
}

// ---------------- K3: out[u][i] = g_l @ g_r^T  (M=128u, N=128i, K=64 single pass) ----------------
__global__ __launch_bounds__(256, 2) void k3_mma(float* __restrict__ out) {
    extern __shared__ __align__(16) char sm[];
    const int t = threadIdx.x, lane = t & 31, w = t >> 5;
    const uint32_t sb = smem_u32(sm);
    const int u0 = blockIdx.x * 128, i0 = blockIdx.y * 128;
    const int m0 = (w >> 2) * 64, n0 = (w & 3) * 32;
    const uint32_t abase = (uint32_t)(m0 + (lane & 15)) * 144 + ((lane >> 4) << 4);
    const uint32_t bbase = (uint32_t)(n0 + (lane & 15)) * 144 + ((lane >> 4) << 4);

#pragma unroll
    for (int q = 0; q < 4; q++) {
        int idx = t + q * 256;
        int row = idx >> 3, c8 = (idx & 7) << 3;
        *(uint4*)(sm + row * 144 + c8 * 2)         = *(const uint4*)(g_l_h + (size_t)(u0 + row) * 64 + c8);
        *(uint4*)(sm + 18432 + row * 144 + c8 * 2) = *(const uint4*)(g_l_l + (size_t)(u0 + row) * 64 + c8);
        *(uint4*)(sm + 36864 + row * 144 + c8 * 2) = *(const uint4*)(g_r_h + (size_t)(i0 + row) * 64 + c8);
        *(uint4*)(sm + 55296 + row * 144 + c8 * 2) = *(const uint4*)(g_r_l + (size_t)(i0 + row) * 64 + c8);
    }
    __syncthreads();

    float acc[4][4][4];
#pragma unroll
    for (int a = 0; a < 4; a++)
#pragma unroll
        for (int b = 0; b < 4; b++)
#pragma unroll
            for (int cc = 0; cc < 4; cc++) acc[a][b][cc] = 0.f;

#pragma unroll
    for (int ks = 0; ks < 4; ks++) {
        uint32_t bh[2][4], bl[2][4];
#pragma unroll
        for (int p = 0; p < 2; p++) {
            ldm4(bh[p], sb + 36864 + bbase + p * 2304 + ks * 32);
            ldm4(bl[p], sb + 55296 + bbase + p * 2304 + ks * 32);
        }
#pragma unroll
        for (int mi = 0; mi < 4; mi++) {
            uint32_t ah[4], al[4];
            ldm4(ah, sb + abase + mi * 2304 + ks * 32);
            ldm4(al, sb + 18432 + abase + mi * 2304 + ks * 32);
#pragma unroll
            for (int nt = 0; nt < 4; nt++) {
                int p = nt >> 1, j = nt & 1;
                mma_bf16(acc[mi][nt], ah, bh[p][j], bh[p][j + 2]);
                mma_bf16(acc[mi][nt], ah, bl[p][j], bl[p][j + 2]);
                mma_bf16(acc[mi][nt], al, bh[p][j], bh[p][j + 2]);
            }
        }
    }

    const int g = lane >> 2, tg = lane & 3;
#pragma unroll
    for (int mi = 0; mi < 4; mi++)
#pragma unroll
        for (int nt = 0; nt < 4; nt++) {
            int row = u0 + m0 + mi * 16 + g;
            int col = i0 + n0 + nt * 8 + tg * 2;
            if (col < ID) {
                if (row < UD)     *(float2*)(out + (size_t)row * ID + col)       = make_float2(acc[mi][nt][0], acc[mi][nt][1]);
                if (row + 8 < UD) *(float2*)(out + (size_t)(row + 8) * ID + col) = make_float2(acc[mi][nt][2], acc[mi][nt][3]);
            }
        }
}

// ---------------- launch ----------------
extern "C" void kernel_launch(void* const* d_in, const int* in_sizes, int n_in,
                              void* d_out, int out_size) {
    const float* lambda_mat = (const float*)d_in[0];
    const float* user_sv    = (const float*)d_in[1];
    const float* item_sv    = (const float*)d_in[2];
    const float* adj_mat    = (const float*)d_in[3];
    const float* norm_adj   = (const float*)d_in[4];
    float* out = (float*)d_out;

    cudaFuncSetAttribute(k1_mma, cudaFuncAttributeMaxDynamicSharedMemorySize, 61440);
    cudaFuncSetAttribute(k2_mma, cudaFuncAttributeMaxDynamicSharedMemorySize, 55296);
    cudaFuncSetAttribute(k3_mma, cudaFuncAttributeMaxDynamicSharedMemorySize, 73728);

    p_item<<<IPAD / 64, 256>>>(item_sv);
    p_user<<<UPAD / 64, 256>>>(user_sv);
    k1_mma<<<dim3(79, 3), 256, 61440>>>(norm_adj);
    k2_mma<<<dim3(94, 3), 256, 55296>>>(adj_mat);
    red_l<<<(UPAD * 64) / 256, 256>>>(lambda_mat);
    red_r<<<(IPAD * 64) / 256, 256>>>();
    k3_mma<<<dim3(79, 94), 256, 73728>>>(out);
}